// round 14
// baseline (speedup 1.0000x reference)
#include <cuda_runtime.h>
#include <mma.h>
#include <cstdint>

using namespace nvcuda;

#define BB   2
#define LL   2048
#define HH   1024
#define NHH  16
#define HDD  64

// tcgen05 is an arch-specific ('a') feature: only emit it in the sm_103a
// arch-specific pass; baseline compute_103 pass gets wmma fallbacks.
#if defined(__CUDA_ARCH__) && (__CUDA_ARCH__ == 1030) && \
    (defined(__CUDA_ARCH_FEAT_SM103_ALL) || defined(__CUDA_ARCH_SPECIFIC__))
#define HAS_TC 1
#else
#define HAS_TC 0
#endif

__device__ float g_q[BB * NHH * LL * HDD];
__device__ float g_k[BB * NHH * LL * HDD];
__device__ float g_v[BB * NHH * LL * HDD];

#define SWZ(x) ((x) ^ (((x) >> 3) & 0x70))

// idesc kind::tf32 (validated): dtype=F32, a/b=TF32, N/8<<17, M/16<<24
#define IDESC_N128 ((1u << 4) | (2u << 7) | (2u << 10) | (16u << 17) | (8u << 24))
#define IDESC_N64  ((1u << 4) | (2u << 7) | (2u << 10) | (8u  << 17) | (8u << 24))

#if HAS_TC
__device__ __forceinline__ uint32_t smem_u32(const void* p) {
    uint32_t a;
    asm("{ .reg .u64 t; cvta.to.shared.u64 t, %1; cvt.u32.u64 %0, t; }"
        : "=r"(a) : "l"(p));
    return a;
}
__device__ __forceinline__ uint32_t elect1() {
    uint32_t r;
    asm volatile("{ .reg .pred p; elect.sync _|p, 0xFFFFFFFF; selp.b32 %0, 1, 0, p; }"
                 : "=r"(r));
    return r;
}
__device__ __forceinline__ uint64_t make_desc(uint32_t base) {
    // K-major SW128 Blackwell: layout=2, version=1, SBO=64, LBO=1
    return (2ULL << 61) | (1ULL << 46) | (64ULL << 32) | (1ULL << 16)
         | ((uint64_t)(base >> 4) & 0x3FFFULL);
}
__device__ __forceinline__ void mma_ss(uint32_t d, uint64_t ad, uint64_t bd,
                                       uint32_t idesc, uint32_t en) {
    asm volatile(
        "{\n\t.reg .pred p;\n\tsetp.ne.u32 p, %4, 0;\n\t"
        "tcgen05.mma.cta_group::1.kind::tf32 [%0], %1, %2, %3, {%5, %5, %5, %5}, p;\n\t}"
        :: "r"(d), "l"(ad), "l"(bd), "r"(idesc), "r"(en), "r"(0u) : "memory");
}
__device__ __forceinline__ void mma_ts(uint32_t d, uint32_t a, uint64_t bd,
                                       uint32_t idesc, uint32_t en) {
    asm volatile(
        "{\n\t.reg .pred p;\n\tsetp.ne.u32 p, %4, 0;\n\t"
        "tcgen05.mma.cta_group::1.kind::tf32 [%0], [%1], %2, %3, {%5, %5, %5, %5}, p;\n\t}"
        :: "r"(d), "r"(a), "l"(bd), "r"(idesc), "r"(en), "r"(0u) : "memory");
}

#define TC_ALLOC(sa, n)  asm volatile("tcgen05.alloc.cta_group::1.sync.aligned.shared::cta.b32 [%0], %1;" :: "r"(sa), "r"(n) : "memory")
#define TC_DEALLOC(t, n) asm volatile("tcgen05.dealloc.cta_group::1.sync.aligned.b32 %0, %1;" :: "r"(t), "r"(n))
#define TC_RELINQ()      asm volatile("tcgen05.relinquish_alloc_permit.cta_group::1.sync.aligned;")
#define TC_COMMIT(mb)    asm volatile("tcgen05.commit.cta_group::1.mbarrier::arrive::one.shared::cluster.b64 [%0];" :: "r"(mb) : "memory")
#define TC_WAIT_LD()     asm volatile("tcgen05.wait::ld.sync.aligned;" ::: "memory")
#define TC_WAIT_ST()     asm volatile("tcgen05.wait::st.sync.aligned;" ::: "memory")
#define TC_FENCE_B()     asm volatile("tcgen05.fence::before_thread_sync;" ::: "memory")
#define TC_FENCE_A()     asm volatile("tcgen05.fence::after_thread_sync;" ::: "memory")
#define PROXY_FENCE()    asm volatile("fence.proxy.async.shared::cta;" ::: "memory")
#define MBAR_INIT(a, c)  asm volatile("mbarrier.init.shared.b64 [%0], %1;" :: "r"(a), "r"(c) : "memory")
#define BAR_SYNC(id, n)  asm volatile("bar.sync %0, %1;" :: "r"(id), "r"(n) : "memory")

#define MBAR_WAIT(mb, ph) do {                                                   \
    uint32_t _m = (mb); uint32_t _p = (ph); uint32_t _d;                         \
    asm volatile("{\n\t.reg .pred p;\n\t"                                        \
        "mbarrier.try_wait.parity.acquire.cta.shared::cta.b64 p, [%1], %2;\n\t"  \
        "selp.b32 %0, 1, 0, p;\n\t}" : "=r"(_d) : "r"(_m), "r"(_p) : "memory");  \
    if (!_d) {                                                                   \
        asm volatile("{\n\t.reg .pred P1;\n\t"                                   \
            "W_%=:\n\t"                                                          \
            "mbarrier.try_wait.parity.acquire.cta.shared::cta.b64 P1, [%0], %1, 0x989680;\n\t" \
            "@P1 bra.uni D_%=;\n\tbra.uni W_%=;\n\tD_%=:\n\t}"                   \
            :: "r"(_m), "r"(_p) : "memory");                                     \
    }                                                                            \
} while (0)

#define TM_LD_X32(r, a)                                                          \
    asm volatile("tcgen05.ld.sync.aligned.32x32b.x32.b32 "                       \
        "{%0,%1,%2,%3,%4,%5,%6,%7,%8,%9,%10,%11,%12,%13,%14,%15,"                \
        "%16,%17,%18,%19,%20,%21,%22,%23,%24,%25,%26,%27,%28,%29,%30,%31}, [%32];" \
        : "=r"((r)[0]),"=r"((r)[1]),"=r"((r)[2]),"=r"((r)[3]),                   \
          "=r"((r)[4]),"=r"((r)[5]),"=r"((r)[6]),"=r"((r)[7]),                   \
          "=r"((r)[8]),"=r"((r)[9]),"=r"((r)[10]),"=r"((r)[11]),                 \
          "=r"((r)[12]),"=r"((r)[13]),"=r"((r)[14]),"=r"((r)[15]),               \
          "=r"((r)[16]),"=r"((r)[17]),"=r"((r)[18]),"=r"((r)[19]),               \
          "=r"((r)[20]),"=r"((r)[21]),"=r"((r)[22]),"=r"((r)[23]),               \
          "=r"((r)[24]),"=r"((r)[25]),"=r"((r)[26]),"=r"((r)[27]),               \
          "=r"((r)[28]),"=r"((r)[29]),"=r"((r)[30]),"=r"((r)[31])                \
        : "r"(a))

#define TM_ST_X32(a, r)                                                          \
    asm volatile("tcgen05.st.sync.aligned.32x32b.x32.b32 [%0], "                 \
        "{%1,%2,%3,%4,%5,%6,%7,%8,%9,%10,%11,%12,%13,%14,%15,%16,"               \
        "%17,%18,%19,%20,%21,%22,%23,%24,%25,%26,%27,%28,%29,%30,%31,%32};"      \
        :: "r"(a),                                                               \
           "r"((r)[0]),"r"((r)[1]),"r"((r)[2]),"r"((r)[3]),                      \
           "r"((r)[4]),"r"((r)[5]),"r"((r)[6]),"r"((r)[7]),                      \
           "r"((r)[8]),"r"((r)[9]),"r"((r)[10]),"r"((r)[11]),                    \
           "r"((r)[12]),"r"((r)[13]),"r"((r)[14]),"r"((r)[15]),                  \
           "r"((r)[16]),"r"((r)[17]),"r"((r)[18]),"r"((r)[19]),                  \
           "r"((r)[20]),"r"((r)[21]),"r"((r)[22]),"r"((r)[23]),                  \
           "r"((r)[24]),"r"((r)[25]),"r"((r)[26]),"r"((r)[27]),                  \
           "r"((r)[28]),"r"((r)[29]),"r"((r)[30]),"r"((r)[31])                   \
        : "memory")
#endif  // HAS_TC

// ===========================================================================
// QKV projection — exact round-6/round-10 passing version (untouched).
// ===========================================================================
#define QSM_PTR   0
#define QSM_MB    8
#define QSM_BIAS  16
#define QSM_A0    2048
#define QSM_STAGE 49152
#define QSM_TOT   (QSM_A0 + 2 * QSM_STAGE)

#define QKV_LDA 40
#define QKV_LDC 132
#define QKV_SMEM_WM ((2 * 128 * QKV_LDA + 128 * QKV_LDC) * (int)sizeof(float))
#define QKV_SMEM (QKV_SMEM_WM + 2048)

__global__ __launch_bounds__(256)
void qkv_proj_kernel(const float* __restrict__ X,
                     const float* __restrict__ Wq, const float* __restrict__ bq,
                     const float* __restrict__ Wk, const float* __restrict__ bk,
                     const float* __restrict__ Wv, const float* __restrict__ bv)
{
    const int z = blockIdx.z;
    const float* __restrict__ W    = (z == 0) ? Wq : (z == 1) ? Wk : Wv;
    const float* __restrict__ bias = (z == 0) ? bq : (z == 1) ? bk : bv;
    float* __restrict__ out        = (z == 0) ? g_q : (z == 1) ? g_k : g_v;

#if HAS_TC
    extern __shared__ char smraw[];
    const uint32_t raw = smem_u32(smraw);
    const uint32_t sb  = (raw + 1023u) & ~1023u;
    char* ab = smraw + (sb - raw);

    const int tid = threadIdx.x;
    const int wid = tid >> 5;
    const int lid = tid & 31;
    const int m0  = blockIdx.y * 128;
    const int n0  = blockIdx.x * 256;

    if (wid == 0) {
        TC_ALLOC(sb + QSM_PTR, 256);
        TC_RELINQ();
    }
    if (tid == 0) MBAR_INIT(sb + QSM_MB, 1);

    *(float*)(ab + QSM_BIAS + tid * 4) = bias[n0 + tid];

    {
#pragma unroll
        for (int u = 0; u < 4; u++) {
            int idx = tid + u * 256;
            int r  = idx >> 3;
            int kb = (idx & 7) << 4;
            float4 xv = *(const float4*)&X[(size_t)(m0 + r) * HH + (kb >> 2)];
            xv.x = wmma::__float_to_tf32(xv.x); xv.y = wmma::__float_to_tf32(xv.y);
            xv.z = wmma::__float_to_tf32(xv.z); xv.w = wmma::__float_to_tf32(xv.w);
            uint32_t off = (uint32_t)((r & 7) * 128 + (r >> 3) * 1024 + kb);
            *(float4*)(ab + QSM_A0 + SWZ(off)) = xv;
        }
#pragma unroll
        for (int u = 0; u < 8; u++) {
            int idx = tid + u * 256;
            int r  = idx >> 3;
            int kb = (idx & 7) << 4;
            float4 wv = *(const float4*)&W[(size_t)(n0 + r) * HH + (kb >> 2)];
            wv.x = wmma::__float_to_tf32(wv.x); wv.y = wmma::__float_to_tf32(wv.y);
            wv.z = wmma::__float_to_tf32(wv.z); wv.w = wmma::__float_to_tf32(wv.w);
            uint32_t off = (uint32_t)((r & 7) * 128 + (r >> 3) * 1024 + kb);
            *(float4*)(ab + QSM_A0 + 16384 + SWZ(off)) = wv;
        }
    }
    PROXY_FENCE();
    __syncthreads();

    const uint32_t tmem = *(const uint32_t*)(ab + QSM_PTR);
    uint64_t adesc[2], bdesc[2];
#pragma unroll
    for (int s = 0; s < 2; s++) {
        adesc[s] = make_desc(sb + QSM_A0 + s * QSM_STAGE);
        bdesc[s] = make_desc(sb + QSM_A0 + s * QSM_STAGE + 16384);
    }

    for (int kt = 0; kt < 32; kt++) {
        const int stage = kt & 1;

        if (wid == 0 && elect1()) {
#pragma unroll
            for (int half = 0; half < 2; half++) {
#pragma unroll
                for (int s = 0; s < 4; s++) {
                    mma_ss(tmem + half * 128,
                           adesc[stage] + (uint64_t)(2 * s),
                           bdesc[stage] + (uint64_t)(half * 1024 + 2 * s),
                           IDESC_N128, (kt > 0 || s > 0) ? 1u : 0u);
                }
            }
            TC_COMMIT(sb + QSM_MB);
        }

        if (kt + 1 < 32) {
            if (kt > 0) { MBAR_WAIT(sb + QSM_MB, (kt - 1) & 1); }
            const int ns = (kt + 1) & 1;
            const int kof = (kt + 1) * 32;
#pragma unroll
            for (int u = 0; u < 4; u++) {
                int idx = tid + u * 256;
                int r  = idx >> 3;
                int kb = (idx & 7) << 4;
                float4 xv = *(const float4*)&X[(size_t)(m0 + r) * HH + kof + (kb >> 2)];
                xv.x = wmma::__float_to_tf32(xv.x); xv.y = wmma::__float_to_tf32(xv.y);
                xv.z = wmma::__float_to_tf32(xv.z); xv.w = wmma::__float_to_tf32(xv.w);
                uint32_t off = (uint32_t)((r & 7) * 128 + (r >> 3) * 1024 + kb);
                *(float4*)(ab + QSM_A0 + ns * QSM_STAGE + SWZ(off)) = xv;
            }
#pragma unroll
            for (int u = 0; u < 8; u++) {
                int idx = tid + u * 256;
                int r  = idx >> 3;
                int kb = (idx & 7) << 4;
                float4 wv = *(const float4*)&W[(size_t)(n0 + r) * HH + kof + (kb >> 2)];
                wv.x = wmma::__float_to_tf32(wv.x); wv.y = wmma::__float_to_tf32(wv.y);
                wv.z = wmma::__float_to_tf32(wv.z); wv.w = wmma::__float_to_tf32(wv.w);
                uint32_t off = (uint32_t)((r & 7) * 128 + (r >> 3) * 1024 + kb);
                *(float4*)(ab + QSM_A0 + ns * QSM_STAGE + 16384 + SWZ(off)) = wv;
            }
            PROXY_FENCE();
        }
        __syncthreads();
    }

    MBAR_WAIT(sb + QSM_MB, 1);
    TC_FENCE_A();
    {
        const int half = wid >> 2;
        const int m = m0 + (wid & 3) * 32 + lid;
        const int b = m >> 11;
        const int l = m & 2047;
        const float* Bias = (const float*)(ab + QSM_BIAS);
#pragma unroll
        for (int c4 = 0; c4 < 4; c4++) {
            const int ncol0 = half * 128 + c4 * 32;
            uint32_t r[32];
            TM_LD_X32(r, tmem + ncol0);
            TC_WAIT_LD();
            const int ng = n0 + ncol0;
            const int h  = ng >> 6;
            const int d0 = ng & 63;
            float* op = out + (((size_t)(b * NHH + h) * LL + l) * HDD + d0);
#pragma unroll
            for (int i = 0; i < 32; i += 4) {
                float4 v;
                v.x = __uint_as_float(r[i + 0]) + Bias[ncol0 + i + 0];
                v.y = __uint_as_float(r[i + 1]) + Bias[ncol0 + i + 1];
                v.z = __uint_as_float(r[i + 2]) + Bias[ncol0 + i + 2];
                v.w = __uint_as_float(r[i + 3]) + Bias[ncol0 + i + 3];
                *(float4*)(op + i) = v;
            }
        }
    }
    __syncthreads();
    if (wid == 0) {
        TC_DEALLOC(tmem, 256);
    }

#else
    extern __shared__ float sm[];
    float* As = sm;
    float* Bs = sm + 128 * QKV_LDA;
    float* Cs = sm + 2 * 128 * QKV_LDA;

    const int tid = threadIdx.x;
    const int wid = tid >> 5;
    const int wm  = (wid >> 2) * 64;
    const int wn  = (wid & 3) * 32;
    const int m0  = blockIdx.y * 128;

    for (int nh = 0; nh < 2; nh++) {
        const int n0 = blockIdx.x * 256 + nh * 128;

        wmma::fragment<wmma::accumulator, 16, 16, 8, float> c[4][2];
#pragma unroll
        for (int i = 0; i < 4; i++)
#pragma unroll
            for (int j = 0; j < 2; j++) wmma::fill_fragment(c[i][j], 0.f);

        for (int k0 = 0; k0 < HH; k0 += 32) {
            __syncthreads();
#pragma unroll
            for (int t = 0; t < 4; t++) {
                int idx = tid + t * 256;
                int row = idx >> 3;
                int c4  = (idx & 7) << 2;
                float4 xa = *(const float4*)&X[(size_t)(m0 + row) * HH + k0 + c4];
                float4 wb = *(const float4*)&W[(size_t)(n0 + row) * HH + k0 + c4];
                float* ap = &As[row * QKV_LDA + c4];
                float* bp = &Bs[row * QKV_LDA + c4];
                ap[0] = wmma::__float_to_tf32(xa.x); ap[1] = wmma::__float_to_tf32(xa.y);
                ap[2] = wmma::__float_to_tf32(xa.z); ap[3] = wmma::__float_to_tf32(xa.w);
                bp[0] = wmma::__float_to_tf32(wb.x); bp[1] = wmma::__float_to_tf32(wb.y);
                bp[2] = wmma::__float_to_tf32(wb.z); bp[3] = wmma::__float_to_tf32(wb.w);
            }
            __syncthreads();
#pragma unroll
            for (int ks = 0; ks < 32; ks += 8) {
                wmma::fragment<wmma::matrix_a, 16, 16, 8, wmma::precision::tf32, wmma::row_major> a[4];
                wmma::fragment<wmma::matrix_b, 16, 16, 8, wmma::precision::tf32, wmma::col_major> b[2];
#pragma unroll
                for (int i = 0; i < 4; i++)
                    wmma::load_matrix_sync(a[i], &As[(wm + i * 16) * QKV_LDA + ks], QKV_LDA);
#pragma unroll
                for (int j = 0; j < 2; j++)
                    wmma::load_matrix_sync(b[j], &Bs[(wn + j * 16) * QKV_LDA + ks], QKV_LDA);
#pragma unroll
                for (int i = 0; i < 4; i++)
#pragma unroll
                    for (int j = 0; j < 2; j++)
                        wmma::mma_sync(c[i][j], a[i], b[j], c[i][j]);
            }
        }
        __syncthreads();
#pragma unroll
        for (int i = 0; i < 4; i++)
#pragma unroll
            for (int j = 0; j < 2; j++)
                wmma::store_matrix_sync(&Cs[(wm + i * 16) * QKV_LDC + wn + j * 16],
                                        c[i][j], QKV_LDC, wmma::mem_row_major);
        __syncthreads();
#pragma unroll
        for (int t = 0; t < 16; t++) {
            int idx = tid + t * 256;
            int row = idx >> 5;
            int c4  = (idx & 31) << 2;
            int m = m0 + row;
            int n = n0 + c4;
            int b = m >> 11;
            int l = m & 2047;
            int h  = n >> 6;
            int d0 = n & 63;
            float4 v;
            v.x = Cs[row * QKV_LDC + c4 + 0] + __ldg(&bias[n + 0]);
            v.y = Cs[row * QKV_LDC + c4 + 1] + __ldg(&bias[n + 1]);
            v.z = Cs[row * QKV_LDC + c4 + 2] + __ldg(&bias[n + 2]);
            v.w = Cs[row * QKV_LDC + c4 + 3] + __ldg(&bias[n + 3]);
            *(float4*)&out[(((size_t)(b * NHH + h) * LL + l) * HDD + d0)] = v;
        }
        __syncthreads();
    }
#endif
}

// ===========================================================================
// Attention — single-mbarrier overlap pipeline.
//   warp 4 per iteration: issue S(t+1) after bar2 (overlaps epilogue(t)),
//   then after bar3 issue PV(t) and make ONE commit covering S(t+1)+PV(t).
//   In-order tensor queue => completion #(t+2) means BOTH done:
//     - epilogue(t) waits parity t&1  (S(t) ready AND PV(t-1) done => P safe)
//     - loaders(t)  waits parity t&1  (PV(t-1) done => stage reusable)
//     - final wait parity 0 (completion #33 = PV(31))
//   This restores the R6 invariant (barrier release covers PV) that R12/R13
//   broke, while keeping the S-MMA off the critical path.
//   TMEM: O[0..64), S0[64..128), S1[128..192), P[192..256)
// ===========================================================================
#define TM_O   0
#define TM_S0  64
#define TM_P   192
#define TM_COLS 256

#define SM_PTR  0
#define SM_MB   8
#define SM_Q    1024
#define KV_STAGE 32768
#define SM_KV0  (SM_Q + 32768)
#define SM_MASK (SM_KV0 + 2 * KV_STAGE)
#define SM_TOT  (SM_MASK + LL * 4)

#define ATT_LD 72
#define ATT_SMEM_TC  (SM_TOT + 1024)
#define ATT_SMEM_WM  (((128 + 64 + 64 + 128) * ATT_LD + 128) * (int)sizeof(float))
#define ATT_SMEM     (ATT_SMEM_WM > ATT_SMEM_TC ? ATT_SMEM_WM : ATT_SMEM_TC)

__global__ __launch_bounds__(256, 2)
void attn_kernel(const float* __restrict__ mask, float* __restrict__ out)
{
#if HAS_TC
    extern __shared__ char smraw[];
    const uint32_t raw = smem_u32(smraw);
    const uint32_t sb  = (raw + 1023u) & ~1023u;
    char* ab = smraw + (sb - raw);

    const int tid = threadIdx.x;
    const int wid = tid >> 5;
    const int lid = tid & 31;
    const int q0  = blockIdx.x * 128;
    const int h   = blockIdx.y;
    const int b   = blockIdx.z;

    const size_t headoff = (size_t)(b * NHH + h) * LL * HDD;
    const float* Qg = g_q + headoff;
    const float* Kg = g_k + headoff;
    const float* Vg = g_v + headoff;
    const float* mkp = mask + (size_t)b * LL;

    if (wid == 4) {
        TC_ALLOC(sb + SM_PTR, TM_COLS);
        TC_RELINQ();
    }
    if (tid == 0) {
        MBAR_INIT(sb + SM_MB, 1);
    }

    // Q tile 128x64 (blocked SW128 K-major, atom-col stride 16KB), rna-rounded
#pragma unroll
    for (int t = 0; t < 8; t++) {
        int idx = tid + t * 256;
        int r  = idx >> 4;
        int kb = (idx & 15) << 4;
        float4 q = *(const float4*)&Qg[(size_t)(q0 + r) * HDD + (kb >> 2)];
        q.x = wmma::__float_to_tf32(q.x); q.y = wmma::__float_to_tf32(q.y);
        q.z = wmma::__float_to_tf32(q.z); q.w = wmma::__float_to_tf32(q.w);
        uint32_t off = (uint32_t)((r & 7) * 128 + (r >> 3) * 1024
                                + (kb & 127) + ((kb >> 7) << 14));
        *(float4*)(ab + SM_Q + SWZ(off)) = q;
    }
    // mask row
#pragma unroll
    for (int t = 0; t < 8; t++) {
        int i = tid + t * 256;
        *(float*)(ab + SM_MASK + i * 4) = mkp[i];
    }
    // K/V tile 0 into stage 0 (loader warps only)
    if (wid >= 4) {
        const int ltid = tid - 128;
        const int vd   = ltid & 63;
        const int vk0  = ltid >> 6;
#pragma unroll
        for (int u = 0; u < 8; u++) {                 // K: 64x64
            int idx = ltid + u * 128;
            int r  = idx >> 4;
            int kb = (idx & 15) << 4;
            float4 k4 = *(const float4*)&Kg[(size_t)r * HDD + (kb >> 2)];
            k4.x = wmma::__float_to_tf32(k4.x); k4.y = wmma::__float_to_tf32(k4.y);
            k4.z = wmma::__float_to_tf32(k4.z); k4.w = wmma::__float_to_tf32(k4.w);
            uint32_t off = (uint32_t)((r & 7) * 128 + (r >> 3) * 1024
                                    + (kb & 127) + ((kb >> 7) << 13));
            *(float4*)(ab + SM_KV0 + SWZ(off)) = k4;
        }
#pragma unroll
        for (int u = 0; u < 8; u++) {                 // V^T: gather 4 kv @ 1 d
            int kv4 = (vk0 + u * 2) * 4;
            float4 w;
            w.x = wmma::__float_to_tf32(Vg[(size_t)(kv4 + 0) * HDD + vd]);
            w.y = wmma::__float_to_tf32(Vg[(size_t)(kv4 + 1) * HDD + vd]);
            w.z = wmma::__float_to_tf32(Vg[(size_t)(kv4 + 2) * HDD + vd]);
            w.w = wmma::__float_to_tf32(Vg[(size_t)(kv4 + 3) * HDD + vd]);
            uint32_t cb = (uint32_t)(kv4 << 2);
            uint32_t off = (uint32_t)((vd & 7) * 128 + (vd >> 3) * 1024)
                         + (cb & 127) + ((cb >> 7) << 13);
            *(float4*)(ab + SM_KV0 + 16384 + SWZ(off)) = w;
        }
    }
    PROXY_FENCE();
    __syncthreads();

    const uint32_t tmem = *(const uint32_t*)(ab + SM_PTR);
    const uint64_t qdesc = make_desc(sb + SM_Q);
    uint64_t kdesc[2], vdesc[2];
#pragma unroll
    for (int s = 0; s < 2; s++) {
        kdesc[s] = make_desc(sb + SM_KV0 + s * KV_STAGE);
        vdesc[s] = make_desc(sb + SM_KV0 + s * KV_STAGE + 16384);
    }
    const float* Msk = (const float*)(ab + SM_MASK);
    const uint32_t woff = (uint32_t)wid << 21;

    // S(0): completion #1 (observed at parity 0)
    if (wid == 4 && elect1()) {
#pragma unroll
        for (int s = 0; s < 8; s++) {
            mma_ss(tmem + TM_S0,
                   qdesc + (uint64_t)((s & 3) * 2 + (s >> 2) * 1024),
                   kdesc[0] + (uint64_t)((s & 3) * 2 + (s >> 2) * 512),
                   IDESC_N64, (s > 0) ? 1u : 0u);
        }
        TC_COMMIT(sb + SM_MB);
    }

    float lsum = 0.f;

    for (int t = 0; t < 32; t++) {
        if (wid >= 4) {
            // ---- loaders: stage K/V(t+1) ----
            if (t < 31) {
                // completion #(t+1) covers PV(t-1): stage (t+1)&1 reusable
                if (t >= 1) { MBAR_WAIT(sb + SM_MB, t & 1); }
                const int ltid = tid - 128;
                const int vd   = ltid & 63;
                const int vk0  = ltid >> 6;
                const int j1   = (t + 1) * 64;
                const uint32_t kvb = SM_KV0 + (uint32_t)(((t + 1) & 1) * KV_STAGE);
#pragma unroll
                for (int u = 0; u < 8; u++) {
                    int idx = ltid + u * 128;
                    int r  = idx >> 4;
                    int kb = (idx & 15) << 4;
                    float4 k4 = *(const float4*)&Kg[(size_t)(j1 + r) * HDD + (kb >> 2)];
                    k4.x = wmma::__float_to_tf32(k4.x); k4.y = wmma::__float_to_tf32(k4.y);
                    k4.z = wmma::__float_to_tf32(k4.z); k4.w = wmma::__float_to_tf32(k4.w);
                    uint32_t off = (uint32_t)((r & 7) * 128 + (r >> 3) * 1024
                                            + (kb & 127) + ((kb >> 7) << 13));
                    *(float4*)(ab + kvb + SWZ(off)) = k4;
                }
#pragma unroll
                for (int u = 0; u < 8; u++) {         // V^T: gather 4 kv @ 1 d
                    int kv4 = (vk0 + u * 2) * 4;
                    float4 w;
                    w.x = wmma::__float_to_tf32(Vg[(size_t)(j1 + kv4 + 0) * HDD + vd]);
                    w.y = wmma::__float_to_tf32(Vg[(size_t)(j1 + kv4 + 1) * HDD + vd]);
                    w.z = wmma::__float_to_tf32(Vg[(size_t)(j1 + kv4 + 2) * HDD + vd]);
                    w.w = wmma::__float_to_tf32(Vg[(size_t)(j1 + kv4 + 3) * HDD + vd]);
                    uint32_t cb = (uint32_t)(kv4 << 2);
                    uint32_t off = (uint32_t)((vd & 7) * 128 + (vd >> 3) * 1024)
                                 + (cb & 127) + ((cb >> 7) << 13);
                    *(float4*)(ab + kvb + 16384 + SWZ(off)) = w;
                }
                PROXY_FENCE();
                BAR_SYNC(2, 128);                  // loaders: K/V(t+1) staged
            }
            if (wid == 4) {
                // ---- EARLY ISSUE of S(t+1): executes during epilogue(t) ----
                if (t < 31 && elect1()) {
                    const uint32_t sd = tmem + TM_S0 + (uint32_t)(((t + 1) & 1) * 64);
#pragma unroll
                    for (int s = 0; s < 8; s++) {
                        mma_ss(sd,
                               qdesc + (uint64_t)((s & 3) * 2 + (s >> 2) * 1024),
                               kdesc[(t + 1) & 1] + (uint64_t)((s & 3) * 2 + (s >> 2) * 512),
                               IDESC_N64, (s > 0) ? 1u : 0u);
                    }
                }
                BAR_SYNC(3, 160);                  // wait P(t) ready
                TC_FENCE_A();
                if (elect1()) {
                    // PV(t): A = P (TMEM), B = V^T[t&1]
#pragma unroll
                    for (int s = 0; s < 8; s++) {
                        mma_ts(tmem + TM_O, tmem + TM_P + s * 8,
                               vdesc[t & 1] + (uint64_t)((s & 3) * 2 + (s >> 2) * 512),
                               IDESC_N64, (t > 0 || s > 0) ? 1u : 0u);
                    }
                    // ONE commit covering S(t+1) AND PV(t): in-order queue =>
                    // barrier fire implies both complete.
                    TC_COMMIT(sb + SM_MB);
                }
            }
        } else {
            // ---- epilogue warps: softmax on S(t) ----
            // completion #(t+1): S(t) ready AND PV(t-1) done (P overwrite safe)
            MBAR_WAIT(sb + SM_MB, t & 1);
            TC_FENCE_A();
            const uint32_t sbase = tmem + TM_S0 + (uint32_t)((t & 1) * 64);
            const int j0 = t * 64;
#pragma unroll
            for (int hf = 0; hf < 2; hf++) {
                uint32_t r[32];
                TM_LD_X32(r, sbase + hf * 32);
                TC_WAIT_LD();
#pragma unroll
                for (int c = 0; c < 32; c++) {
                    float u = __expf(__uint_as_float(r[c]) * 0.125f
                                     + Msk[j0 + hf * 32 + c]);
                    lsum += u;
                    r[c] = __float_as_uint(wmma::__float_to_tf32(u));
                }
                TM_ST_X32(tmem + TM_P + hf * 32 + woff, r);
            }
            TC_WAIT_ST();
            TC_FENCE_B();
            BAR_SYNC(3, 160);                      // P(t) ready
        }
    }

    // final: completion #33 (iter-31 commit, covers PV(31)), parity 0
    if (wid < 4) {
        MBAR_WAIT(sb + SM_MB, 0);
        TC_FENCE_A();
        const int q = q0 + wid * 32 + lid;
        const float inv = 1.f / lsum;
        float* op = out + ((size_t)b * LL + q) * HH + h * HDD;
#pragma unroll
        for (int hf = 0; hf < 2; hf++) {
            uint32_t r[32];
            TM_LD_X32(r, tmem + TM_O + hf * 32);
            TC_WAIT_LD();
#pragma unroll
            for (int c = 0; c < 32; c += 4) {
                float4 o;
                o.x = __uint_as_float(r[c + 0]) * inv;
                o.y = __uint_as_float(r[c + 1]) * inv;
                o.z = __uint_as_float(r[c + 2]) * inv;
                o.w = __uint_as_float(r[c + 3]) * inv;
                *(float4*)(op + hf * 32 + c) = o;
            }
        }
    }
    __syncthreads();
    if (wid == 4) {
        TC_DEALLOC(tmem, TM_COLS);
    }

#else
    // ---------------- wmma fallback (never runs on GB300) ----------------
    extern __shared__ float smf[];
    float* Qs = smf;
    float* Ks = Qs + 128 * ATT_LD;
    float* Vs = Ks + 64 * ATT_LD;
    float* Ps = Vs + 64 * ATT_LD;
    float* Ls = Ps + 128 * ATT_LD;

    const int tid = threadIdx.x;
    const int wid = tid >> 5;
    const int q0  = blockIdx.x * 128;
    const int h   = blockIdx.y;
    const int b   = blockIdx.z;

    const size_t headoff = (size_t)(b * NHH + h) * LL * HDD;
    const float* Qg = g_q + headoff;
    const float* Kg = g_k + headoff;
    const float* Vg = g_v + headoff;
    const float* mkp = mask + (size_t)b * LL;

#pragma unroll
    for (int t = 0; t < 8; t++) {
        int idx = tid + t * 256;
        int r  = idx >> 4;
        int d4 = (idx & 15) << 2;
        float4 q = *(const float4*)&Qg[(size_t)(q0 + r) * HDD + d4];
        float* p = &Qs[r * ATT_LD + d4];
        p[0] = wmma::__float_to_tf32(q.x); p[1] = wmma::__float_to_tf32(q.y);
        p[2] = wmma::__float_to_tf32(q.z); p[3] = wmma::__float_to_tf32(q.w);
    }

    wmma::fragment<wmma::accumulator, 16, 16, 8, float> o[4];
#pragma unroll
    for (int j = 0; j < 4; j++) wmma::fill_fragment(o[j], 0.f);

    const int srow  = tid >> 1;
    const int shalf = (tid & 1) * 32;
    float lsum = 0.f;
    const int mrow = wid * 16;

    for (int j0 = 0; j0 < LL; j0 += 64) {
        __syncthreads();
#pragma unroll
        for (int t = 0; t < 4; t++) {
            int idx = tid + t * 256;
            int r  = idx >> 4;
            int d4 = (idx & 15) << 2;
            float4 k4 = *(const float4*)&Kg[(size_t)(j0 + r) * HDD + d4];
            float4 v4 = *(const float4*)&Vg[(size_t)(j0 + r) * HDD + d4];
            float* kp = &Ks[r * ATT_LD + d4];
            float* vp = &Vs[r * ATT_LD + d4];
            kp[0] = wmma::__float_to_tf32(k4.x); kp[1] = wmma::__float_to_tf32(k4.y);
            kp[2] = wmma::__float_to_tf32(k4.z); kp[3] = wmma::__float_to_tf32(k4.w);
            vp[0] = wmma::__float_to_tf32(v4.x); vp[1] = wmma::__float_to_tf32(v4.y);
            vp[2] = wmma::__float_to_tf32(v4.z); vp[3] = wmma::__float_to_tf32(v4.w);
        }
        __syncthreads();

        {
            wmma::fragment<wmma::accumulator, 16, 16, 8, float> s[4];
#pragma unroll
            for (int j = 0; j < 4; j++) wmma::fill_fragment(s[j], 0.f);
#pragma unroll
            for (int k = 0; k < 64; k += 8) {
                wmma::fragment<wmma::matrix_a, 16, 16, 8, wmma::precision::tf32, wmma::row_major> a;
                wmma::load_matrix_sync(a, &Qs[mrow * ATT_LD + k], ATT_LD);
#pragma unroll
                for (int j = 0; j < 4; j++) {
                    wmma::fragment<wmma::matrix_b, 16, 16, 8, wmma::precision::tf32, wmma::col_major> bf;
                    wmma::load_matrix_sync(bf, &Ks[(j * 16) * ATT_LD + k], ATT_LD);
                    wmma::mma_sync(s[j], a, bf, s[j]);
                }
            }
#pragma unroll
            for (int j = 0; j < 4; j++)
                wmma::store_matrix_sync(&Ps[mrow * ATT_LD + j * 16], s[j],
                                        ATT_LD, wmma::mem_row_major);
        }
        __syncthreads();

        {
            float* pr = &Ps[srow * ATT_LD + shalf];
            const float* mr = &mkp[j0 + shalf];
#pragma unroll
            for (int cc = 0; cc < 32; cc++) {
                float u = __expf(pr[cc] * 0.125f + mr[cc]);
                lsum += u;
                pr[cc] = wmma::__float_to_tf32(u);
            }
        }
        __syncthreads();

#pragma unroll
        for (int k = 0; k < 64; k += 8) {
            wmma::fragment<wmma::matrix_a, 16, 16, 8, wmma::precision::tf32, wmma::row_major> a;
            wmma::load_matrix_sync(a, &Ps[mrow * ATT_LD + k], ATT_LD);
#pragma unroll
            for (int j = 0; j < 4; j++) {
                wmma::fragment<wmma::matrix_b, 16, 16, 8, wmma::precision::tf32, wmma::row_major> bf;
                wmma::load_matrix_sync(bf, &Vs[k * ATT_LD + j * 16], ATT_LD);
                wmma::mma_sync(o[j], a, bf, o[j]);
            }
        }
    }

    {
        float tot = lsum + __shfl_xor_sync(0xffffffffu, lsum, 1);
        if ((tid & 1) == 0) Ls[srow] = tot;
    }
    __syncthreads();

#pragma unroll
    for (int j = 0; j < 4; j++)
        wmma::store_matrix_sync(&Qs[mrow * ATT_LD + j * 16], o[j],
                                ATT_LD, wmma::mem_row_major);
    __syncthreads();

#pragma unroll
    for (int t = 0; t < 8; t++) {
        int idx = tid + t * 256;
        int r  = idx >> 4;
        int d4 = (idx & 15) << 2;
        float inv = 1.f / Ls[r];
        float4 v;
        v.x = Qs[r * ATT_LD + d4 + 0] * inv;
        v.y = Qs[r * ATT_LD + d4 + 1] * inv;
        v.z = Qs[r * ATT_LD + d4 + 2] * inv;
        v.w = Qs[r * ATT_LD + d4 + 3] * inv;
        *(float4*)&out[((size_t)b * LL + q0 + r) * HH + h * HDD + d4] = v;
    }
#endif
}

// ===========================================================================
extern "C" void kernel_launch(void* const* d_in, const int* in_sizes, int n_in,
                              void* d_out, int out_size)
{
    (void)in_sizes; (void)n_in; (void)out_size;

    const float* hs   = (const float*)d_in[0];
    const float* mask = (const float*)d_in[1];
    const float* Wq   = (const float*)d_in[2];
    const float* bq   = (const float*)d_in[3];
    const float* Wk   = (const float*)d_in[4];
    const float* bk   = (const float*)d_in[5];
    const float* Wv   = (const float*)d_in[6];
    const float* bv   = (const float*)d_in[7];
    float* out = (float*)d_out;

    int smem1 = QKV_SMEM;
    cudaFuncSetAttribute(qkv_proj_kernel,
                         cudaFuncAttributeMaxDynamicSharedMemorySize, smem1);
    dim3 g1(HH / 256, (BB * LL) / 128, 3);
    qkv_proj_kernel<<<g1, 256, smem1>>>(hs, Wq, bq, Wk, bk, Wv, bv);

    int smem2 = ATT_SMEM;
    cudaFuncSetAttribute(attn_kernel,
                         cudaFuncAttributeMaxDynamicSharedMemorySize, smem2);
    dim3 g2(LL / 128, NHH, BB);
    attn_kernel<<<g2, 256, smem2>>>(mask, out);
}

// round 17
// speedup vs baseline: 1.0191x; 1.0191x over previous
#include <cuda_runtime.h>
#include <mma.h>
#include <cstdint>

using namespace nvcuda;

#define BB   2
#define LL   2048
#define HH   1024
#define NHH  16
#define HDD  64

// tcgen05 is an arch-specific ('a') feature: only emit it in the sm_103a
// arch-specific pass; baseline compute_103 pass gets wmma fallbacks.
#if defined(__CUDA_ARCH__) && (__CUDA_ARCH__ == 1030) && \
    (defined(__CUDA_ARCH_FEAT_SM103_ALL) || defined(__CUDA_ARCH_SPECIFIC__))
#define HAS_TC 1
#else
#define HAS_TC 0
#endif

__device__ float g_q[BB * NHH * LL * HDD];
__device__ float g_k[BB * NHH * LL * HDD];
__device__ float g_v[BB * NHH * LL * HDD];

#define SWZ(x) ((x) ^ (((x) >> 3) & 0x70))

// idesc kind::tf32 (validated): dtype=F32, a/b=TF32, N/8<<17, M/16<<24
#define IDESC_N128 ((1u << 4) | (2u << 7) | (2u << 10) | (16u << 17) | (8u << 24))
#define IDESC_N64  ((1u << 4) | (2u << 7) | (2u << 10) | (8u  << 17) | (8u << 24))

#if HAS_TC
__device__ __forceinline__ uint32_t smem_u32(const void* p) {
    uint32_t a;
    asm("{ .reg .u64 t; cvta.to.shared.u64 t, %1; cvt.u32.u64 %0, t; }"
        : "=r"(a) : "l"(p));
    return a;
}
__device__ __forceinline__ uint32_t elect1() {
    uint32_t r;
    asm volatile("{ .reg .pred p; elect.sync _|p, 0xFFFFFFFF; selp.b32 %0, 1, 0, p; }"
                 : "=r"(r));
    return r;
}
__device__ __forceinline__ uint64_t make_desc(uint32_t base) {
    // K-major SW128 Blackwell: layout=2, version=1, SBO=64, LBO=1
    return (2ULL << 61) | (1ULL << 46) | (64ULL << 32) | (1ULL << 16)
         | ((uint64_t)(base >> 4) & 0x3FFFULL);
}
__device__ __forceinline__ void mma_ss(uint32_t d, uint64_t ad, uint64_t bd,
                                       uint32_t idesc, uint32_t en) {
    asm volatile(
        "{\n\t.reg .pred p;\n\tsetp.ne.u32 p, %4, 0;\n\t"
        "tcgen05.mma.cta_group::1.kind::tf32 [%0], %1, %2, %3, {%5, %5, %5, %5}, p;\n\t}"
        :: "r"(d), "l"(ad), "l"(bd), "r"(idesc), "r"(en), "r"(0u) : "memory");
}
__device__ __forceinline__ void mma_ts(uint32_t d, uint32_t a, uint64_t bd,
                                       uint32_t idesc, uint32_t en) {
    asm volatile(
        "{\n\t.reg .pred p;\n\tsetp.ne.u32 p, %4, 0;\n\t"
        "tcgen05.mma.cta_group::1.kind::tf32 [%0], [%1], %2, %3, {%5, %5, %5, %5}, p;\n\t}"
        :: "r"(d), "r"(a), "l"(bd), "r"(idesc), "r"(en), "r"(0u) : "memory");
}

#define TC_ALLOC(sa, n)  asm volatile("tcgen05.alloc.cta_group::1.sync.aligned.shared::cta.b32 [%0], %1;" :: "r"(sa), "r"(n) : "memory")
#define TC_DEALLOC(t, n) asm volatile("tcgen05.dealloc.cta_group::1.sync.aligned.b32 %0, %1;" :: "r"(t), "r"(n))
#define TC_RELINQ()      asm volatile("tcgen05.relinquish_alloc_permit.cta_group::1.sync.aligned;")
#define TC_COMMIT(mb)    asm volatile("tcgen05.commit.cta_group::1.mbarrier::arrive::one.shared::cluster.b64 [%0];" :: "r"(mb) : "memory")
#define TC_WAIT_LD()     asm volatile("tcgen05.wait::ld.sync.aligned;" ::: "memory")
#define TC_WAIT_ST()     asm volatile("tcgen05.wait::st.sync.aligned;" ::: "memory")
#define TC_FENCE_B()     asm volatile("tcgen05.fence::before_thread_sync;" ::: "memory")
#define TC_FENCE_A()     asm volatile("tcgen05.fence::after_thread_sync;" ::: "memory")
#define PROXY_FENCE()    asm volatile("fence.proxy.async.shared::cta;" ::: "memory")
#define MBAR_INIT(a, c)  asm volatile("mbarrier.init.shared.b64 [%0], %1;" :: "r"(a), "r"(c) : "memory")
#define BAR_SYNC(id, n)  asm volatile("bar.sync %0, %1;" :: "r"(id), "r"(n) : "memory")

#define MBAR_WAIT(mb, ph) do {                                                   \
    uint32_t _m = (mb); uint32_t _p = (ph); uint32_t _d;                         \
    asm volatile("{\n\t.reg .pred p;\n\t"                                        \
        "mbarrier.try_wait.parity.acquire.cta.shared::cta.b64 p, [%1], %2;\n\t"  \
        "selp.b32 %0, 1, 0, p;\n\t}" : "=r"(_d) : "r"(_m), "r"(_p) : "memory");  \
    if (!_d) {                                                                   \
        asm volatile("{\n\t.reg .pred P1;\n\t"                                   \
            "W_%=:\n\t"                                                          \
            "mbarrier.try_wait.parity.acquire.cta.shared::cta.b64 P1, [%0], %1, 0x989680;\n\t" \
            "@P1 bra.uni D_%=;\n\tbra.uni W_%=;\n\tD_%=:\n\t}"                   \
            :: "r"(_m), "r"(_p) : "memory");                                     \
    }                                                                            \
} while (0)

#define TM_LD_X32(r, a)                                                          \
    asm volatile("tcgen05.ld.sync.aligned.32x32b.x32.b32 "                       \
        "{%0,%1,%2,%3,%4,%5,%6,%7,%8,%9,%10,%11,%12,%13,%14,%15,"                \
        "%16,%17,%18,%19,%20,%21,%22,%23,%24,%25,%26,%27,%28,%29,%30,%31}, [%32];" \
        : "=r"((r)[0]),"=r"((r)[1]),"=r"((r)[2]),"=r"((r)[3]),                   \
          "=r"((r)[4]),"=r"((r)[5]),"=r"((r)[6]),"=r"((r)[7]),                   \
          "=r"((r)[8]),"=r"((r)[9]),"=r"((r)[10]),"=r"((r)[11]),                 \
          "=r"((r)[12]),"=r"((r)[13]),"=r"((r)[14]),"=r"((r)[15]),               \
          "=r"((r)[16]),"=r"((r)[17]),"=r"((r)[18]),"=r"((r)[19]),               \
          "=r"((r)[20]),"=r"((r)[21]),"=r"((r)[22]),"=r"((r)[23]),               \
          "=r"((r)[24]),"=r"((r)[25]),"=r"((r)[26]),"=r"((r)[27]),               \
          "=r"((r)[28]),"=r"((r)[29]),"=r"((r)[30]),"=r"((r)[31])                \
        : "r"(a))

#define TM_ST_X32(a, r)                                                          \
    asm volatile("tcgen05.st.sync.aligned.32x32b.x32.b32 [%0], "                 \
        "{%1,%2,%3,%4,%5,%6,%7,%8,%9,%10,%11,%12,%13,%14,%15,%16,"               \
        "%17,%18,%19,%20,%21,%22,%23,%24,%25,%26,%27,%28,%29,%30,%31,%32};"      \
        :: "r"(a),                                                               \
           "r"((r)[0]),"r"((r)[1]),"r"((r)[2]),"r"((r)[3]),                      \
           "r"((r)[4]),"r"((r)[5]),"r"((r)[6]),"r"((r)[7]),                      \
           "r"((r)[8]),"r"((r)[9]),"r"((r)[10]),"r"((r)[11]),                    \
           "r"((r)[12]),"r"((r)[13]),"r"((r)[14]),"r"((r)[15]),                  \
           "r"((r)[16]),"r"((r)[17]),"r"((r)[18]),"r"((r)[19]),                  \
           "r"((r)[20]),"r"((r)[21]),"r"((r)[22]),"r"((r)[23]),                  \
           "r"((r)[24]),"r"((r)[25]),"r"((r)[26]),"r"((r)[27]),                  \
           "r"((r)[28]),"r"((r)[29]),"r"((r)[30]),"r"((r)[31])                   \
        : "memory")
#endif  // HAS_TC

// ===========================================================================
// QKV projection — EXACT round-10/round-11 passing version. DO NOT TOUCH:
// every perturbation of this kernel (prefetch R7/R9/R15, launch-bounds R16)
// has deadlocked on hardware.
// ===========================================================================
#define QSM_PTR   0
#define QSM_MB    8
#define QSM_BIAS  16
#define QSM_A0    2048
#define QSM_STAGE 49152
#define QSM_TOT   (QSM_A0 + 2 * QSM_STAGE)

#define QKV_LDA 40
#define QKV_LDC 132
#define QKV_SMEM_WM ((2 * 128 * QKV_LDA + 128 * QKV_LDC) * (int)sizeof(float))
#define QKV_SMEM (QKV_SMEM_WM + 2048)

__global__ __launch_bounds__(256)
void qkv_proj_kernel(const float* __restrict__ X,
                     const float* __restrict__ Wq, const float* __restrict__ bq,
                     const float* __restrict__ Wk, const float* __restrict__ bk,
                     const float* __restrict__ Wv, const float* __restrict__ bv)
{
    const int z = blockIdx.z;
    const float* __restrict__ W    = (z == 0) ? Wq : (z == 1) ? Wk : Wv;
    const float* __restrict__ bias = (z == 0) ? bq : (z == 1) ? bk : bv;
    float* __restrict__ out        = (z == 0) ? g_q : (z == 1) ? g_k : g_v;

#if HAS_TC
    extern __shared__ char smraw[];
    const uint32_t raw = smem_u32(smraw);
    const uint32_t sb  = (raw + 1023u) & ~1023u;
    char* ab = smraw + (sb - raw);

    const int tid = threadIdx.x;
    const int wid = tid >> 5;
    const int lid = tid & 31;
    const int m0  = blockIdx.y * 128;
    const int n0  = blockIdx.x * 256;

    if (wid == 0) {
        TC_ALLOC(sb + QSM_PTR, 256);
        TC_RELINQ();
    }
    if (tid == 0) MBAR_INIT(sb + QSM_MB, 1);

    *(float*)(ab + QSM_BIAS + tid * 4) = bias[n0 + tid];

    {
#pragma unroll
        for (int u = 0; u < 4; u++) {
            int idx = tid + u * 256;
            int r  = idx >> 3;
            int kb = (idx & 7) << 4;
            float4 xv = *(const float4*)&X[(size_t)(m0 + r) * HH + (kb >> 2)];
            xv.x = wmma::__float_to_tf32(xv.x); xv.y = wmma::__float_to_tf32(xv.y);
            xv.z = wmma::__float_to_tf32(xv.z); xv.w = wmma::__float_to_tf32(xv.w);
            uint32_t off = (uint32_t)((r & 7) * 128 + (r >> 3) * 1024 + kb);
            *(float4*)(ab + QSM_A0 + SWZ(off)) = xv;
        }
#pragma unroll
        for (int u = 0; u < 8; u++) {
            int idx = tid + u * 256;
            int r  = idx >> 3;
            int kb = (idx & 7) << 4;
            float4 wv = *(const float4*)&W[(size_t)(n0 + r) * HH + (kb >> 2)];
            wv.x = wmma::__float_to_tf32(wv.x); wv.y = wmma::__float_to_tf32(wv.y);
            wv.z = wmma::__float_to_tf32(wv.z); wv.w = wmma::__float_to_tf32(wv.w);
            uint32_t off = (uint32_t)((r & 7) * 128 + (r >> 3) * 1024 + kb);
            *(float4*)(ab + QSM_A0 + 16384 + SWZ(off)) = wv;
        }
    }
    PROXY_FENCE();
    __syncthreads();

    const uint32_t tmem = *(const uint32_t*)(ab + QSM_PTR);
    uint64_t adesc[2], bdesc[2];
#pragma unroll
    for (int s = 0; s < 2; s++) {
        adesc[s] = make_desc(sb + QSM_A0 + s * QSM_STAGE);
        bdesc[s] = make_desc(sb + QSM_A0 + s * QSM_STAGE + 16384);
    }

    for (int kt = 0; kt < 32; kt++) {
        const int stage = kt & 1;

        if (wid == 0 && elect1()) {
#pragma unroll
            for (int half = 0; half < 2; half++) {
#pragma unroll
                for (int s = 0; s < 4; s++) {
                    mma_ss(tmem + half * 128,
                           adesc[stage] + (uint64_t)(2 * s),
                           bdesc[stage] + (uint64_t)(half * 1024 + 2 * s),
                           IDESC_N128, (kt > 0 || s > 0) ? 1u : 0u);
                }
            }
            TC_COMMIT(sb + QSM_MB);
        }

        if (kt + 1 < 32) {
            if (kt > 0) { MBAR_WAIT(sb + QSM_MB, (kt - 1) & 1); }
            const int ns = (kt + 1) & 1;
            const int kof = (kt + 1) * 32;
#pragma unroll
            for (int u = 0; u < 4; u++) {
                int idx = tid + u * 256;
                int r  = idx >> 3;
                int kb = (idx & 7) << 4;
                float4 xv = *(const float4*)&X[(size_t)(m0 + r) * HH + kof + (kb >> 2)];
                xv.x = wmma::__float_to_tf32(xv.x); xv.y = wmma::__float_to_tf32(xv.y);
                xv.z = wmma::__float_to_tf32(xv.z); xv.w = wmma::__float_to_tf32(xv.w);
                uint32_t off = (uint32_t)((r & 7) * 128 + (r >> 3) * 1024 + kb);
                *(float4*)(ab + QSM_A0 + ns * QSM_STAGE + SWZ(off)) = xv;
            }
#pragma unroll
            for (int u = 0; u < 8; u++) {
                int idx = tid + u * 256;
                int r  = idx >> 3;
                int kb = (idx & 7) << 4;
                float4 wv = *(const float4*)&W[(size_t)(n0 + r) * HH + kof + (kb >> 2)];
                wv.x = wmma::__float_to_tf32(wv.x); wv.y = wmma::__float_to_tf32(wv.y);
                wv.z = wmma::__float_to_tf32(wv.z); wv.w = wmma::__float_to_tf32(wv.w);
                uint32_t off = (uint32_t)((r & 7) * 128 + (r >> 3) * 1024 + kb);
                *(float4*)(ab + QSM_A0 + ns * QSM_STAGE + 16384 + SWZ(off)) = wv;
            }
            PROXY_FENCE();
        }
        __syncthreads();
    }

    MBAR_WAIT(sb + QSM_MB, 1);
    TC_FENCE_A();
    {
        const int half = wid >> 2;
        const int m = m0 + (wid & 3) * 32 + lid;
        const int b = m >> 11;
        const int l = m & 2047;
        const float* Bias = (const float*)(ab + QSM_BIAS);
#pragma unroll
        for (int c4 = 0; c4 < 4; c4++) {
            const int ncol0 = half * 128 + c4 * 32;
            uint32_t r[32];
            TM_LD_X32(r, tmem + ncol0);
            TC_WAIT_LD();
            const int ng = n0 + ncol0;
            const int h  = ng >> 6;
            const int d0 = ng & 63;
            float* op = out + (((size_t)(b * NHH + h) * LL + l) * HDD + d0);
#pragma unroll
            for (int i = 0; i < 32; i += 4) {
                float4 v;
                v.x = __uint_as_float(r[i + 0]) + Bias[ncol0 + i + 0];
                v.y = __uint_as_float(r[i + 1]) + Bias[ncol0 + i + 1];
                v.z = __uint_as_float(r[i + 2]) + Bias[ncol0 + i + 2];
                v.w = __uint_as_float(r[i + 3]) + Bias[ncol0 + i + 3];
                *(float4*)(op + i) = v;
            }
        }
    }
    __syncthreads();
    if (wid == 0) {
        TC_DEALLOC(tmem, 256);
    }

#else
    extern __shared__ float sm[];
    float* As = sm;
    float* Bs = sm + 128 * QKV_LDA;
    float* Cs = sm + 2 * 128 * QKV_LDA;

    const int tid = threadIdx.x;
    const int wid = tid >> 5;
    const int wm  = (wid >> 2) * 64;
    const int wn  = (wid & 3) * 32;
    const int m0  = blockIdx.y * 128;

    for (int nh = 0; nh < 2; nh++) {
        const int n0 = blockIdx.x * 256 + nh * 128;

        wmma::fragment<wmma::accumulator, 16, 16, 8, float> c[4][2];
#pragma unroll
        for (int i = 0; i < 4; i++)
#pragma unroll
            for (int j = 0; j < 2; j++) wmma::fill_fragment(c[i][j], 0.f);

        for (int k0 = 0; k0 < HH; k0 += 32) {
            __syncthreads();
#pragma unroll
            for (int t = 0; t < 4; t++) {
                int idx = tid + t * 256;
                int row = idx >> 3;
                int c4  = (idx & 7) << 2;
                float4 xa = *(const float4*)&X[(size_t)(m0 + row) * HH + k0 + c4];
                float4 wb = *(const float4*)&W[(size_t)(n0 + row) * HH + k0 + c4];
                float* ap = &As[row * QKV_LDA + c4];
                float* bp = &Bs[row * QKV_LDA + c4];
                ap[0] = wmma::__float_to_tf32(xa.x); ap[1] = wmma::__float_to_tf32(xa.y);
                ap[2] = wmma::__float_to_tf32(xa.z); ap[3] = wmma::__float_to_tf32(xa.w);
                bp[0] = wmma::__float_to_tf32(wb.x); bp[1] = wmma::__float_to_tf32(wb.y);
                bp[2] = wmma::__float_to_tf32(wb.z); bp[3] = wmma::__float_to_tf32(wb.w);
            }
            __syncthreads();
#pragma unroll
            for (int ks = 0; ks < 32; ks += 8) {
                wmma::fragment<wmma::matrix_a, 16, 16, 8, wmma::precision::tf32, wmma::row_major> a[4];
                wmma::fragment<wmma::matrix_b, 16, 16, 8, wmma::precision::tf32, wmma::col_major> b[2];
#pragma unroll
                for (int i = 0; i < 4; i++)
                    wmma::load_matrix_sync(a[i], &As[(wm + i * 16) * QKV_LDA + ks], QKV_LDA);
#pragma unroll
                for (int j = 0; j < 2; j++)
                    wmma::load_matrix_sync(b[j], &Bs[(wn + j * 16) * QKV_LDA + ks], QKV_LDA);
#pragma unroll
                for (int i = 0; i < 4; i++)
#pragma unroll
                    for (int j = 0; j < 2; j++)
                        wmma::mma_sync(c[i][j], a[i], b[j], c[i][j]);
            }
        }
        __syncthreads();
#pragma unroll
        for (int i = 0; i < 4; i++)
#pragma unroll
            for (int j = 0; j < 2; j++)
                wmma::store_matrix_sync(&Cs[(wm + i * 16) * QKV_LDC + wn + j * 16],
                                        c[i][j], QKV_LDC, wmma::mem_row_major);
        __syncthreads();
#pragma unroll
        for (int t = 0; t < 16; t++) {
            int idx = tid + t * 256;
            int row = idx >> 5;
            int c4  = (idx & 31) << 2;
            int m = m0 + row;
            int n = n0 + c4;
            int b = m >> 11;
            int l = m & 2047;
            int h  = n >> 6;
            int d0 = n & 63;
            float4 v;
            v.x = Cs[row * QKV_LDC + c4 + 0] + __ldg(&bias[n + 0]);
            v.y = Cs[row * QKV_LDC + c4 + 1] + __ldg(&bias[n + 1]);
            v.z = Cs[row * QKV_LDC + c4 + 2] + __ldg(&bias[n + 2]);
            v.w = Cs[row * QKV_LDC + c4 + 3] + __ldg(&bias[n + 3]);
            *(float4*)&out[(((size_t)(b * NHH + h) * LL + l) * HDD + d0)] = v;
        }
        __syncthreads();
    }
#endif
}

// ===========================================================================
// Attention — round-11 base; ONE epilogue-local change: both LDTMs issued
// before a single TC_WAIT_LD and both STTMs before a single TC_WAIT_ST
// (pattern verified in test_mma_mxf8.cu). No sync/commit/wait reordering.
//   warps 0-3: softmax epilogue; warps 4-7: K/V loaders; warp 4: MMA issuer.
//   TMEM: O[0..64), S0[64..128), S1[128..192), P[192..256)
// ===========================================================================
#define TM_O   0
#define TM_S0  64
#define TM_P   192
#define TM_COLS 256

#define SM_PTR  0
#define SM_MBS  8
#define SM_MBO  16
#define SM_Q    1024
#define KV_STAGE 32768
#define SM_KV0  (SM_Q + 32768)
#define SM_MASK (SM_KV0 + 2 * KV_STAGE)
#define SM_TOT  (SM_MASK + LL * 4)

#define ATT_LD 72
#define ATT_SMEM_TC  (SM_TOT + 1024)
#define ATT_SMEM_WM  (((128 + 64 + 64 + 128) * ATT_LD + 128) * (int)sizeof(float))
#define ATT_SMEM     (ATT_SMEM_WM > ATT_SMEM_TC ? ATT_SMEM_WM : ATT_SMEM_TC)

__global__ __launch_bounds__(256, 2)
void attn_kernel(const float* __restrict__ mask, float* __restrict__ out)
{
#if HAS_TC
    extern __shared__ char smraw[];
    const uint32_t raw = smem_u32(smraw);
    const uint32_t sb  = (raw + 1023u) & ~1023u;
    char* ab = smraw + (sb - raw);

    const int tid = threadIdx.x;
    const int wid = tid >> 5;
    const int lid = tid & 31;
    const int q0  = blockIdx.x * 128;
    const int h   = blockIdx.y;
    const int b   = blockIdx.z;

    const size_t headoff = (size_t)(b * NHH + h) * LL * HDD;
    const float* Qg = g_q + headoff;
    const float* Kg = g_k + headoff;
    const float* Vg = g_v + headoff;
    const float* mkp = mask + (size_t)b * LL;

    if (wid == 4) {
        TC_ALLOC(sb + SM_PTR, TM_COLS);
        TC_RELINQ();
    }
    if (tid == 0) {
        MBAR_INIT(sb + SM_MBS, 1);
        MBAR_INIT(sb + SM_MBO, 1);
    }

    // Q tile 128x64 (blocked SW128 K-major, atom-col stride 16KB), rna-rounded
#pragma unroll
    for (int t = 0; t < 8; t++) {
        int idx = tid + t * 256;
        int r  = idx >> 4;
        int kb = (idx & 15) << 4;
        float4 q = *(const float4*)&Qg[(size_t)(q0 + r) * HDD + (kb >> 2)];
        q.x = wmma::__float_to_tf32(q.x); q.y = wmma::__float_to_tf32(q.y);
        q.z = wmma::__float_to_tf32(q.z); q.w = wmma::__float_to_tf32(q.w);
        uint32_t off = (uint32_t)((r & 7) * 128 + (r >> 3) * 1024
                                + (kb & 127) + ((kb >> 7) << 14));
        *(float4*)(ab + SM_Q + SWZ(off)) = q;
    }
    // mask row
#pragma unroll
    for (int t = 0; t < 8; t++) {
        int i = tid + t * 256;
        *(float*)(ab + SM_MASK + i * 4) = mkp[i];
    }
    // K/V tile 0 into stage 0 (loader warps only)
    if (wid >= 4) {
        const int ltid = tid - 128;
        const int vd   = ltid & 63;
        const int vk0  = ltid >> 6;
#pragma unroll
        for (int u = 0; u < 8; u++) {                 // K: 64x64
            int idx = ltid + u * 128;
            int r  = idx >> 4;
            int kb = (idx & 15) << 4;
            float4 k4 = *(const float4*)&Kg[(size_t)r * HDD + (kb >> 2)];
            k4.x = wmma::__float_to_tf32(k4.x); k4.y = wmma::__float_to_tf32(k4.y);
            k4.z = wmma::__float_to_tf32(k4.z); k4.w = wmma::__float_to_tf32(k4.w);
            uint32_t off = (uint32_t)((r & 7) * 128 + (r >> 3) * 1024
                                    + (kb & 127) + ((kb >> 7) << 13));
            *(float4*)(ab + SM_KV0 + SWZ(off)) = k4;
        }
#pragma unroll
        for (int u = 0; u < 8; u++) {                 // V^T: gather 4 kv @ 1 d
            int kv4 = (vk0 + u * 2) * 4;
            float4 w;
            w.x = wmma::__float_to_tf32(Vg[(size_t)(kv4 + 0) * HDD + vd]);
            w.y = wmma::__float_to_tf32(Vg[(size_t)(kv4 + 1) * HDD + vd]);
            w.z = wmma::__float_to_tf32(Vg[(size_t)(kv4 + 2) * HDD + vd]);
            w.w = wmma::__float_to_tf32(Vg[(size_t)(kv4 + 3) * HDD + vd]);
            uint32_t cb = (uint32_t)(kv4 << 2);
            uint32_t off = (uint32_t)((vd & 7) * 128 + (vd >> 3) * 1024)
                         + (cb & 127) + ((cb >> 7) << 13);
            *(float4*)(ab + SM_KV0 + 16384 + SWZ(off)) = w;
        }
    }
    PROXY_FENCE();
    __syncthreads();

    const uint32_t tmem = *(const uint32_t*)(ab + SM_PTR);
    const uint64_t qdesc = make_desc(sb + SM_Q);
    uint64_t kdesc[2], vdesc[2];
#pragma unroll
    for (int s = 0; s < 2; s++) {
        kdesc[s] = make_desc(sb + SM_KV0 + s * KV_STAGE);
        vdesc[s] = make_desc(sb + SM_KV0 + s * KV_STAGE + 16384);
    }
    const float* Msk = (const float*)(ab + SM_MASK);
    const uint32_t woff = (uint32_t)wid << 21;

    // S(0)
    if (wid == 4 && elect1()) {
#pragma unroll
        for (int s = 0; s < 8; s++) {
            mma_ss(tmem + TM_S0,
                   qdesc + (uint64_t)((s & 3) * 2 + (s >> 2) * 1024),
                   kdesc[0] + (uint64_t)((s & 3) * 2 + (s >> 2) * 512),
                   IDESC_N64, (s > 0) ? 1u : 0u);
        }
        TC_COMMIT(sb + SM_MBS);
    }

    float lsum = 0.f;

    for (int t = 0; t < 32; t++) {
        if (wid >= 4) {
            // ---- loaders: stage K/V(t+1), then warp4 issues PV(t) / S(t+1) ----
            if (t < 31) {
                if (t >= 1) { MBAR_WAIT(sb + SM_MBO, (t - 1) & 1); }
                const int ltid = tid - 128;
                const int vd   = ltid & 63;
                const int vk0  = ltid >> 6;
                const int j1   = (t + 1) * 64;
                const uint32_t kvb = SM_KV0 + (uint32_t)(((t + 1) & 1) * KV_STAGE);
#pragma unroll
                for (int u = 0; u < 8; u++) {
                    int idx = ltid + u * 128;
                    int r  = idx >> 4;
                    int kb = (idx & 15) << 4;
                    float4 k4 = *(const float4*)&Kg[(size_t)(j1 + r) * HDD + (kb >> 2)];
                    k4.x = wmma::__float_to_tf32(k4.x); k4.y = wmma::__float_to_tf32(k4.y);
                    k4.z = wmma::__float_to_tf32(k4.z); k4.w = wmma::__float_to_tf32(k4.w);
                    uint32_t off = (uint32_t)((r & 7) * 128 + (r >> 3) * 1024
                                            + (kb & 127) + ((kb >> 7) << 13));
                    *(float4*)(ab + kvb + SWZ(off)) = k4;
                }
#pragma unroll
                for (int u = 0; u < 8; u++) {         // V^T: gather 4 kv @ 1 d
                    int kv4 = (vk0 + u * 2) * 4;
                    float4 w;
                    w.x = wmma::__float_to_tf32(Vg[(size_t)(j1 + kv4 + 0) * HDD + vd]);
                    w.y = wmma::__float_to_tf32(Vg[(size_t)(j1 + kv4 + 1) * HDD + vd]);
                    w.z = wmma::__float_to_tf32(Vg[(size_t)(j1 + kv4 + 2) * HDD + vd]);
                    w.w = wmma::__float_to_tf32(Vg[(size_t)(j1 + kv4 + 3) * HDD + vd]);
                    uint32_t cb = (uint32_t)(kv4 << 2);
                    uint32_t off = (uint32_t)((vd & 7) * 128 + (vd >> 3) * 1024)
                                 + (cb & 127) + ((cb >> 7) << 13);
                    *(float4*)(ab + kvb + 16384 + SWZ(off)) = w;
                }
                PROXY_FENCE();
                BAR_SYNC(2, 128);                  // loaders: K/V(t+1) staged
            }
            if (wid == 4) {
                BAR_SYNC(3, 160);                  // wait P(t) ready
                TC_FENCE_A();
                if (elect1()) {
                    // PV(t): A = P (TMEM), B = V^T[t&1]
#pragma unroll
                    for (int s = 0; s < 8; s++) {
                        mma_ts(tmem + TM_O, tmem + TM_P + s * 8,
                               vdesc[t & 1] + (uint64_t)((s & 3) * 2 + (s >> 2) * 512),
                               IDESC_N64, (t > 0 || s > 0) ? 1u : 0u);
                    }
                    TC_COMMIT(sb + SM_MBO);
                    if (t < 31) {
                        // S(t+1) into S[(t+1)&1]
                        const uint32_t sd = tmem + TM_S0 + (uint32_t)(((t + 1) & 1) * 64);
#pragma unroll
                        for (int s = 0; s < 8; s++) {
                            mma_ss(sd,
                                   qdesc + (uint64_t)((s & 3) * 2 + (s >> 2) * 1024),
                                   kdesc[(t + 1) & 1] + (uint64_t)((s & 3) * 2 + (s >> 2) * 512),
                                   IDESC_N64, (s > 0) ? 1u : 0u);
                        }
                        TC_COMMIT(sb + SM_MBS);
                    }
                }
            }
        } else {
            // ---- epilogue warps: softmax on S(t) ----
            MBAR_WAIT(sb + SM_MBS, t & 1);
            TC_FENCE_A();
            const uint32_t sbase = tmem + TM_S0 + (uint32_t)((t & 1) * 64);
            const int j0 = t * 64;
            uint32_t r[64];
            TM_LD_X32(r,      sbase);         // both LDs before one wait
            TM_LD_X32(r + 32, sbase + 32);    // (pattern per test_mma_mxf8.cu)
            TC_WAIT_LD();
#pragma unroll
            for (int c = 0; c < 64; c++) {
                float u = __expf(__uint_as_float(r[c]) * 0.125f + Msk[j0 + c]);
                lsum += u;
                r[c] = __float_as_uint(wmma::__float_to_tf32(u));
            }
            TM_ST_X32(tmem + TM_P + woff,      r);
            TM_ST_X32(tmem + TM_P + 32 + woff, r + 32);
            TC_WAIT_ST();
            TC_FENCE_B();
            BAR_SYNC(3, 160);                      // P(t) ready
        }
    }

    // final: O is complete after PV(31)
    if (wid < 4) {
        MBAR_WAIT(sb + SM_MBO, 1);
        TC_FENCE_A();
        const int q = q0 + wid * 32 + lid;
        const float inv = 1.f / lsum;
        float* op = out + ((size_t)b * LL + q) * HH + h * HDD;
        uint32_t r[64];
        TM_LD_X32(r,      tmem + TM_O);
        TM_LD_X32(r + 32, tmem + TM_O + 32);
        TC_WAIT_LD();
#pragma unroll
        for (int c = 0; c < 64; c += 4) {
            float4 o;
            o.x = __uint_as_float(r[c + 0]) * inv;
            o.y = __uint_as_float(r[c + 1]) * inv;
            o.z = __uint_as_float(r[c + 2]) * inv;
            o.w = __uint_as_float(r[c + 3]) * inv;
            *(float4*)(op + c) = o;
        }
    }
    __syncthreads();
    if (wid == 4) {
        TC_DEALLOC(tmem, TM_COLS);
    }

#else
    // ---------------- wmma fallback (never runs on GB300) ----------------
    extern __shared__ float smf[];
    float* Qs = smf;
    float* Ks = Qs + 128 * ATT_LD;
    float* Vs = Ks + 64 * ATT_LD;
    float* Ps = Vs + 64 * ATT_LD;
    float* Ls = Ps + 128 * ATT_LD;

    const int tid = threadIdx.x;
    const int wid = tid >> 5;
    const int q0  = blockIdx.x * 128;
    const int h   = blockIdx.y;
    const int b   = blockIdx.z;

    const size_t headoff = (size_t)(b * NHH + h) * LL * HDD;
    const float* Qg = g_q + headoff;
    const float* Kg = g_k + headoff;
    const float* Vg = g_v + headoff;
    const float* mkp = mask + (size_t)b * LL;

#pragma unroll
    for (int t = 0; t < 8; t++) {
        int idx = tid + t * 256;
        int r  = idx >> 4;
        int d4 = (idx & 15) << 2;
        float4 q = *(const float4*)&Qg[(size_t)(q0 + r) * HDD + d4];
        float* p = &Qs[r * ATT_LD + d4];
        p[0] = wmma::__float_to_tf32(q.x); p[1] = wmma::__float_to_tf32(q.y);
        p[2] = wmma::__float_to_tf32(q.z); p[3] = wmma::__float_to_tf32(q.w);
    }

    wmma::fragment<wmma::accumulator, 16, 16, 8, float> o[4];
#pragma unroll
    for (int j = 0; j < 4; j++) wmma::fill_fragment(o[j], 0.f);

    const int srow  = tid >> 1;
    const int shalf = (tid & 1) * 32;
    float lsum = 0.f;
    const int mrow = wid * 16;

    for (int j0 = 0; j0 < LL; j0 += 64) {
        __syncthreads();
#pragma unroll
        for (int t = 0; t < 4; t++) {
            int idx = tid + t * 256;
            int r  = idx >> 4;
            int d4 = (idx & 15) << 2;
            float4 k4 = *(const float4*)&Kg[(size_t)(j0 + r) * HDD + d4];
            float4 v4 = *(const float4*)&Vg[(size_t)(j0 + r) * HDD + d4];
            float* kp = &Ks[r * ATT_LD + d4];
            float* vp = &Vs[r * ATT_LD + d4];
            kp[0] = wmma::__float_to_tf32(k4.x); kp[1] = wmma::__float_to_tf32(k4.y);
            kp[2] = wmma::__float_to_tf32(k4.z); kp[3] = wmma::__float_to_tf32(k4.w);
            vp[0] = wmma::__float_to_tf32(v4.x); vp[1] = wmma::__float_to_tf32(v4.y);
            vp[2] = wmma::__float_to_tf32(v4.z); vp[3] = wmma::__float_to_tf32(v4.w);
        }
        __syncthreads();

        {
            wmma::fragment<wmma::accumulator, 16, 16, 8, float> s[4];
#pragma unroll
            for (int j = 0; j < 4; j++) wmma::fill_fragment(s[j], 0.f);
#pragma unroll
            for (int k = 0; k < 64; k += 8) {
                wmma::fragment<wmma::matrix_a, 16, 16, 8, wmma::precision::tf32, wmma::row_major> a;
                wmma::load_matrix_sync(a, &Qs[mrow * ATT_LD + k], ATT_LD);
#pragma unroll
                for (int j = 0; j < 4; j++) {
                    wmma::fragment<wmma::matrix_b, 16, 16, 8, wmma::precision::tf32, wmma::col_major> bf;
                    wmma::load_matrix_sync(bf, &Ks[(j * 16) * ATT_LD + k], ATT_LD);
                    wmma::mma_sync(s[j], a, bf, s[j]);
                }
            }
#pragma unroll
            for (int j = 0; j < 4; j++)
                wmma::store_matrix_sync(&Ps[mrow * ATT_LD + j * 16], s[j],
                                        ATT_LD, wmma::mem_row_major);
        }
        __syncthreads();

        {
            float* pr = &Ps[srow * ATT_LD + shalf];
            const float* mr = &mkp[j0 + shalf];
#pragma unroll
            for (int cc = 0; cc < 32; cc++) {
                float u = __expf(pr[cc] * 0.125f + mr[cc]);
                lsum += u;
                pr[cc] = wmma::__float_to_tf32(u);
            }
        }
        __syncthreads();

#pragma unroll
        for (int k = 0; k < 64; k += 8) {
            wmma::fragment<wmma::matrix_a, 16, 16, 8, wmma::precision::tf32, wmma::row_major> a;
            wmma::load_matrix_sync(a, &Ps[mrow * ATT_LD + k], ATT_LD);
#pragma unroll
            for (int j = 0; j < 4; j++) {
                wmma::fragment<wmma::matrix_b, 16, 16, 8, wmma::precision::tf32, wmma::row_major> bf;
                wmma::load_matrix_sync(bf, &Vs[k * ATT_LD + j * 16], ATT_LD);
                wmma::mma_sync(o[j], a, bf, o[j]);
            }
        }
    }

    {
        float tot = lsum + __shfl_xor_sync(0xffffffffu, lsum, 1);
        if ((tid & 1) == 0) Ls[srow] = tot;
    }
    __syncthreads();

#pragma unroll
    for (int j = 0; j < 4; j++)
        wmma::store_matrix_sync(&Qs[mrow * ATT_LD + j * 16], o[j],
                                ATT_LD, wmma::mem_row_major);
    __syncthreads();

#pragma unroll
    for (int t = 0; t < 8; t++) {
        int idx = tid + t * 256;
        int r  = idx >> 4;
        int d4 = (idx & 15) << 2;
        float inv = 1.f / Ls[r];
        float4 v;
        v.x = Qs[r * ATT_LD + d4 + 0] * inv;
        v.y = Qs[r * ATT_LD + d4 + 1] * inv;
        v.z = Qs[r * ATT_LD + d4 + 2] * inv;
        v.w = Qs[r * ATT_LD + d4 + 3] * inv;
        *(float4*)&out[((size_t)b * LL + q0 + r) * HH + h * HDD + d4] = v;
    }
#endif
}

// ===========================================================================
extern "C" void kernel_launch(void* const* d_in, const int* in_sizes, int n_in,
                              void* d_out, int out_size)
{
    (void)in_sizes; (void)n_in; (void)out_size;

    const float* hs   = (const float*)d_in[0];
    const float* mask = (const float*)d_in[1];
    const float* Wq   = (const float*)d_in[2];
    const float* bq   = (const float*)d_in[3];
    const float* Wk   = (const float*)d_in[4];
    const float* bk   = (const float*)d_in[5];
    const float* Wv   = (const float*)d_in[6];
    const float* bv   = (const float*)d_in[7];
    float* out = (float*)d_out;

    int smem1 = QKV_SMEM;
    cudaFuncSetAttribute(qkv_proj_kernel,
                         cudaFuncAttributeMaxDynamicSharedMemorySize, smem1);
    dim3 g1(HH / 256, (BB * LL) / 128, 3);
    qkv_proj_kernel<<<g1, 256, smem1>>>(hs, Wq, bq, Wk, bk, Wv, bv);

    int smem2 = ATT_SMEM;
    cudaFuncSetAttribute(attn_kernel,
                         cudaFuncAttributeMaxDynamicSharedMemorySize, smem2);
    dim3 g2(LL / 128, NHH, BB);
    attn_kernel<<<g2, 256, smem2>>>(mask, out);
}